// round 7
// baseline (speedup 1.0000x reference)
#include <cuda_runtime.h>
#include <cuda_bf16.h>
#include <cuda_fp8.h>
#include <cstdint>
#include <math.h>

#define N_SPK 2048
#define M_UTT 16
#define D_EMB 512
#define NM (N_SPK * M_UTT)
#define EPSF 1e-8f
#define QSCALE 16.0f                    // fp8 quantization scale; S = acc / 256

// ---------------- scratch (allocation-free rule: __device__ globals) -------
__device__ unsigned char g_vnq[NM * D_EMB];     // normalized utterances, e4m3 (x16)
__device__ unsigned char g_Cnq[N_SPK * D_EMB];  // normalized centroids,  e4m3 (x16)
__device__ float g_sdiag[NM];                   // cos(C_min[j], v_j) fp32-exact
__device__ float g_sself[NM];                   // raw scaled dot (256*S) of fp8 values
__device__ float g_colsum[NM];                  // sum_n exp(w*(S[n,j]-1))

// ---------------- helpers ---------------------------------------------------
__device__ __forceinline__ uint32_t smem_u32(const void* p) {
    uint32_t a;
    asm("{ .reg .u64 t; cvta.to.shared.u64 t, %1; cvt.u32.u64 %0, t; }" : "=r"(a) : "l"(p));
    return a;
}
__device__ __forceinline__ void cp16(uint32_t s, const void* g) {
    asm volatile("cp.async.cg.shared.global [%0], [%1], 16;" :: "r"(s), "l"(g) : "memory");
}
__device__ __forceinline__ void cp_commit() { asm volatile("cp.async.commit_group;" ::: "memory"); }
__device__ __forceinline__ void cp_wait1()  { asm volatile("cp.async.wait_group 1;" ::: "memory"); }
__device__ __forceinline__ float ex2a(float x) {
    float r; asm("ex2.approx.f32 %0, %1;" : "=f"(r) : "f"(x)); return r;
}
#define MMA_FP8(d, a0, a1, a2, a3, b0, b1)                                    \
    asm volatile(                                                             \
        "mma.sync.aligned.m16n8k32.row.col.f32.e4m3.e4m3.f32 "                \
        "{%0,%1,%2,%3}, {%4,%5,%6,%7}, {%8,%9}, {%0,%1,%2,%3};"               \
        : "+f"(d[0]), "+f"(d[1]), "+f"(d[2]), "+f"(d[3])                      \
        : "r"(a0), "r"(a1), "r"(a2), "r"(a3), "r"(b0), "r"(b1))

__device__ __forceinline__ unsigned char q_e4m3(float x) {
    return (unsigned char)__nv_cvt_float_to_fp8(x, __NV_SATFINITE, __NV_E4M3);
}
__device__ __forceinline__ float dq_e4m3(unsigned char b) {
    return __half2float(__nv_cvt_fp8_to_halfraw((__nv_fp8_storage_t)b, __NV_E4M3));
}

// ---------------- init ------------------------------------------------------
__global__ void init_kernel(float* out) {
    if (blockIdx.x == 0 && threadIdx.x == 0) *out = 0.0f;
}

// ---------------- prep: per-speaker normalize + quantize + diag terms ------
__global__ __launch_bounds__(256) void prep_kernel(const float* __restrict__ v) {
    __shared__ float sv[M_UTT * D_EMB];
    __shared__ float red[8][33];
    __shared__ float fin[33];

    const int tid = threadIdx.x;
    const int n = blockIdx.x;

    {
        const float4* src = (const float4*)(v + (size_t)n * M_UTT * D_EMB);
        float4* dst = (float4*)sv;
        #pragma unroll
        for (int i = 0; i < (M_UTT * D_EMB / 4) / 256; i++)
            dst[tid + i * 256] = src[tid + i * 256];
    }
    __syncthreads();

    float s0 = 0.0f, s1 = 0.0f;
    #pragma unroll
    for (int m = 0; m < M_UTT; m++) {
        s0 += sv[m * D_EMB + tid];
        s1 += sv[m * D_EMB + tid + 256];
    }

    float vals[33];
    #pragma unroll
    for (int m = 0; m < M_UTT; m++) {
        float x0 = sv[m * D_EMB + tid];
        float x1 = sv[m * D_EMB + tid + 256];
        vals[m]      = x0 * x0 + x1 * x1;   // ||v_m||^2 partial
        vals[16 + m] = s0 * x0 + s1 * x1;   // ssum.v_m partial
    }
    vals[32] = s0 * s0 + s1 * s1;           // ||ssum||^2 partial

    #pragma unroll
    for (int i = 0; i < 33; i++) {
        float x = vals[i];
        #pragma unroll
        for (int o = 16; o > 0; o >>= 1) x += __shfl_xor_sync(0xffffffffu, x, o);
        vals[i] = x;
    }
    const int warp = tid >> 5, lane = tid & 31;
    if (lane == 0) {
        #pragma unroll
        for (int i = 0; i < 33; i++) red[warp][i] = vals[i];
    }
    __syncthreads();
    if (tid < 33) {
        float x = 0.0f;
        #pragma unroll
        for (int w = 0; w < 8; w++) x += red[w][tid];
        fin[tid] = x;
    }
    __syncthreads();

    const float ss = fin[32];
    const float cinv = QSCALE / fmaxf(sqrtf(ss), (float)M_UTT * EPSF);

    unsigned char cq0 = q_e4m3(s0 * cinv);
    unsigned char cq1 = q_e4m3(s1 * cinv);
    g_Cnq[n * D_EMB + tid]       = cq0;
    g_Cnq[n * D_EMB + tid + 256] = cq1;
    const float fc0 = dq_e4m3(cq0);
    const float fc1 = dq_e4m3(cq1);

    float sfp[16];
    #pragma unroll
    for (int m = 0; m < M_UTT; m++) {
        float rv = QSCALE / fmaxf(sqrtf(fin[m]), EPSF);
        unsigned char vq0 = q_e4m3(sv[m * D_EMB + tid] * rv);
        unsigned char vq1 = q_e4m3(sv[m * D_EMB + tid + 256] * rv);
        size_t base = (size_t)(n * M_UTT + m) * D_EMB;
        g_vnq[base + tid]       = vq0;
        g_vnq[base + tid + 256] = vq1;
        sfp[m] = fc0 * dq_e4m3(vq0) + fc1 * dq_e4m3(vq1);   // scaled (256*S) dot
    }

    #pragma unroll
    for (int m = 0; m < 16; m++) {
        float x = sfp[m];
        #pragma unroll
        for (int o = 16; o > 0; o >>= 1) x += __shfl_xor_sync(0xffffffffu, x, o);
        sfp[m] = x;
    }
    if (lane == 0) {
        #pragma unroll
        for (int m = 0; m < 16; m++) red[warp][m] = sfp[m];
    }
    __syncthreads();
    if (tid < 16) {
        float x = 0.0f;
        #pragma unroll
        for (int w = 0; w < 8; w++) x += red[w][tid];
        g_sself[n * M_UTT + tid] = x;       // raw scaled dot (matches GEMM acc)

        float sq  = fin[tid];
        float dsv = fin[16 + tid];
        float nv  = fmaxf(sqrtf(sq), EPSF);
        float cm2 = fmaxf(ss - 2.0f * dsv + sq, 0.0f);
        const float invMm1 = 1.0f / (float)(M_UTT - 1);
        float ncm = fmaxf(sqrtf(cm2) * invMm1, EPSF);
        g_sdiag[n * M_UTT + tid] = ((dsv - sq) * invMm1) / (ncm * nv);
    }
}

// ---------------- fp8 mma.sync GEMM + fused exp rowsum ----------------------
// acc[u,s] = 256 * vn[u,:].Cn[s,:]; A tile (128 x 512 fp8) resident; B (Cn)
// streamed in BK=64 chunks of 256 speakers. Warp m64 x n64; CTA 128 x 256.
// 8 N-tiles x 8 K-chunks = 64 iterations, 2 k32 MMA steps per chunk.
#define A_PITCHB 528                   // bytes per A row (512 + 16 pad)
#define A_PITCHW 132
#define B_PITCHB 80                    // bytes per B row (64 + 16 pad)
#define B_PITCHW 20
#define SA_BYTES (128 * A_PITCHB)      // 67584
#define SB_BYTES (256 * B_PITCHB)      // 20480 per buffer
#define SB_OFF   SA_BYTES
#define SRED_OFF (SB_OFF + 2 * SB_BYTES)   // 108544
#define SMEM_SZ  (SRED_OFF + 4 * 128 * 4)  // 110592

__global__ __launch_bounds__(256, 1) void gemm_lse_kernel(const float* __restrict__ wp) {
    extern __shared__ char smem[];
    const uint32_t sbase = smem_u32(smem);
    const uint32_t* As32 = (const uint32_t*)smem;
    float* red = (float*)(smem + SRED_OFF);

    const int tid = threadIdx.x;
    const int lane = tid & 31, wid = tid >> 5;
    const int warpM = wid & 1;            // 2 warps over M=128
    const int warpN = wid >> 1;           // 4 warps over N=256
    const int g = lane >> 2, t = lane & 3;
    const int uttBase = blockIdx.x * 128;

    // ---- stage A (128 x 512 fp8, padded rows); group 0 with B chunk 0 -----
    {
        const unsigned char* vsrc = g_vnq + (size_t)uttBase * D_EMB;
        #pragma unroll 8
        for (int i = 0; i < 16; i++) {
            int flat = tid + 256 * i;          // 0..4095
            int row = flat >> 5, cc = flat & 31;
            cp16(sbase + row * A_PITCHB + cc * 16,
                 vsrc + (size_t)row * D_EMB + cc * 16);
        }
    }
    // B chunk c (ntile = c>>3 covers 256 speakers, kc = c&7 covers 64 bytes)
    auto loadB = [&](int c, int buf) {
        const int ntile = c >> 3, kc = c & 7;
        const unsigned char* bsrc = g_Cnq + (size_t)(ntile * 256) * D_EMB + kc * 64;
        const uint32_t bb = sbase + SB_OFF + buf * SB_BYTES;
        #pragma unroll
        for (int i = 0; i < 4; i++) {
            int flat = tid + 256 * i;          // 0..1023
            int row = flat >> 2, k16 = flat & 3;
            cp16(bb + row * B_PITCHB + k16 * 16,
                 bsrc + (size_t)row * D_EMB + k16 * 16);
        }
    };
    loadB(0, 0); cp_commit();
    loadB(1, 1); cp_commit();

    const float wv = *wp;
    const float c1 = wv * 1.44269504f;         // w * log2(e)
    const float c0 = -c1;
    const float c1s = c1 * (1.0f / (QSCALE * QSCALE));  // acc -> w*log2e*S

    float acc[4][8][4];                        // 128 accumulators
    #pragma unroll
    for (int i = 0; i < 4; i++)
        #pragma unroll
        for (int j = 0; j < 8; j++)
            #pragma unroll
            for (int r = 0; r < 4; r++) acc[i][j][r] = 0.0f;
    float rs[4][2] = {{0,0},{0,0},{0,0},{0,0}};

    #pragma unroll 1
    for (int c = 0; c < 64; c++) {
        const int buf = c & 1;
        cp_wait1();
        __syncthreads();

        const uint32_t* B32 = (const uint32_t*)(smem + SB_OFF + buf * SB_BYTES);
        const int kbw = (c & 7) * 16;          // A word base for this k64 chunk

        #pragma unroll
        for (int s = 0; s < 2; s++) {          // two k32 steps
            uint32_t ra[4][4];
            #pragma unroll
            for (int i = 0; i < 4; i++) {
                const int arow = warpM * 64 + i * 16 + g;
                const int wi = arow * A_PITCHW + kbw + s * 8 + t;
                ra[i][0] = As32[wi];                       // row g,   k 4t
                ra[i][1] = As32[wi + 8 * A_PITCHW];        // row g+8, k 4t
                ra[i][2] = As32[wi + 4];                   // row g,   k 16+4t
                ra[i][3] = As32[wi + 8 * A_PITCHW + 4];    // row g+8, k 16+4t
            }
            #pragma unroll
            for (int j = 0; j < 8; j++) {
                const int nrow = warpN * 64 + j * 8 + g;
                const int wj = nrow * B_PITCHW + s * 8 + t;
                const uint32_t rb0 = B32[wj];              // n g, k 4t
                const uint32_t rb1 = B32[wj + 4];          // n g, k 16+4t
                #pragma unroll
                for (int i = 0; i < 4; i++)
                    MMA_FP8(acc[i][j], ra[i][0], ra[i][1], ra[i][2], ra[i][3], rb0, rb1);
            }
        }

        __syncthreads();                       // all warps done reading buf
        if (c + 2 < 64) loadB(c + 2, buf);
        cp_commit();                           // one group per iteration

        if ((c & 7) == 7) {                    // N-tile done: exp into rowsums
            #pragma unroll
            for (int i = 0; i < 4; i++) {
                float a0 = 0.0f, a1 = 0.0f;
                #pragma unroll
                for (int j = 0; j < 8; j++) {
                    a0 += ex2a(fmaf(acc[i][j][0], c1s, c0)) + ex2a(fmaf(acc[i][j][1], c1s, c0));
                    a1 += ex2a(fmaf(acc[i][j][2], c1s, c0)) + ex2a(fmaf(acc[i][j][3], c1s, c0));
                    acc[i][j][0] = acc[i][j][1] = acc[i][j][2] = acc[i][j][3] = 0.0f;
                }
                rs[i][0] += a0;
                rs[i][1] += a1;
            }
        }
    }

    // ---- reduce rowsums: quad (t spans n-pairs) then across warpN ---------
    #pragma unroll
    for (int i = 0; i < 4; i++)
        #pragma unroll
        for (int r = 0; r < 2; r++) {
            float x = rs[i][r];
            x += __shfl_xor_sync(0xffffffffu, x, 1);
            x += __shfl_xor_sync(0xffffffffu, x, 2);
            rs[i][r] = x;
        }
    if (t == 0) {
        #pragma unroll
        for (int i = 0; i < 4; i++)
            #pragma unroll
            for (int r = 0; r < 2; r++)
                red[warpN * 128 + warpM * 64 + i * 16 + r * 8 + g] = rs[i][r];
    }
    __syncthreads();
    if (tid < 128)
        g_colsum[uttBase + tid] =
            (red[tid] + red[128 + tid]) + (red[256 + tid] + red[384 + tid]);
}

// ---------------- final loss ------------------------------------------------
__global__ __launch_bounds__(256) void loss_kernel(const float* __restrict__ wp,
                                                   float* __restrict__ out) {
    __shared__ float rsm[8];
    const int j = blockIdx.x * blockDim.x + threadIdx.x;
    const float wv = *wp;
    const float c1 = wv * 1.44269504f;
    const float c0 = -c1;
    const float c1s = c1 * (1.0f / (QSCALE * QSCALE));
    float L = 0.0f;
    if (j < NM) {
        float sd = g_sdiag[j];
        float sf = g_sself[j];              // raw scaled dot, same c1s as epilogue
        float cs = g_colsum[j] - ex2a(fmaf(sf, c1s, c0)) + ex2a(fmaf(sd, c1, c0));
        L = wv * (1.0f - sd) + logf(cs);
    }
    #pragma unroll
    for (int o = 16; o > 0; o >>= 1) L += __shfl_xor_sync(0xffffffffu, L, o);
    const int warp = threadIdx.x >> 5, lane = threadIdx.x & 31;
    if (lane == 0) rsm[warp] = L;
    __syncthreads();
    if (threadIdx.x == 0) {
        float tacc = 0.0f;
        #pragma unroll
        for (int w = 0; w < 8; w++) tacc += rsm[w];
        atomicAdd(out, tacc);
    }
}

// ---------------------------------------------------------------------------
extern "C" void kernel_launch(void* const* d_in, const int* in_sizes, int n_in,
                              void* d_out, int out_size) {
    const float* v  = (const float*)d_in[0];   // [NM, D] fp32
    const float* wp = (const float*)d_in[1];   // scalar w (b cancels analytically)
    float* out = (float*)d_out;

    cudaFuncSetAttribute(gemm_lse_kernel,
                         cudaFuncAttributeMaxDynamicSharedMemorySize, SMEM_SZ);

    init_kernel<<<1, 32>>>(out);
    prep_kernel<<<N_SPK, 256>>>(v);
    gemm_lse_kernel<<<NM / 128, 256, SMEM_SZ>>>(wp);
    loss_kernel<<<NM / 256, 256>>>(wp, out);
}

// round 8
// speedup vs baseline: 1.2016x; 1.2016x over previous
#include <cuda_runtime.h>
#include <cuda_bf16.h>
#include <cstdint>
#include <math.h>

#define N_SPK 2048
#define M_UTT 16
#define D_EMB 512
#define NM (N_SPK * M_UTT)
#define EPSF 1e-8f
#define GRID_GEMM 152                  // GB300: 152 SMs, persistent 1 CTA/SM
#define NUNITS 2048                    // 256 mtiles x 8 ntiles

// ---------------- scratch (allocation-free rule: __device__ globals) -------
__device__ __nv_bfloat16 g_vnb[NM * D_EMB];     // normalized utterances, bf16
__device__ __nv_bfloat16 g_Cnb[N_SPK * D_EMB];  // normalized centroids,  bf16
__device__ float g_sdiag[NM];                   // cos(C_min[j], v_j) fp32-exact
__device__ float g_sself[NM];                   // dot of bf16-rounded Cn,vn
__device__ float g_colsum[NM];                  // sum_n exp(w*(S[n,j]-1))

// ---------------- helpers ---------------------------------------------------
__device__ __forceinline__ uint32_t smem_u32(const void* p) {
    uint32_t a;
    asm("{ .reg .u64 t; cvta.to.shared.u64 t, %1; cvt.u32.u64 %0, t; }" : "=r"(a) : "l"(p));
    return a;
}
__device__ __forceinline__ void cp16(uint32_t s, const void* g) {
    asm volatile("cp.async.cg.shared.global [%0], [%1], 16;" :: "r"(s), "l"(g) : "memory");
}
__device__ __forceinline__ void cp_commit() { asm volatile("cp.async.commit_group;" ::: "memory"); }
__device__ __forceinline__ void cp_wait1()  { asm volatile("cp.async.wait_group 1;" ::: "memory"); }
__device__ __forceinline__ float ex2a(float x) {
    float r; asm("ex2.approx.f32 %0, %1;" : "=f"(r) : "f"(x)); return r;
}
#define MMA_BF16(d, a0, a1, a2, a3, b0, b1)                                   \
    asm volatile(                                                             \
        "mma.sync.aligned.m16n8k16.row.col.f32.bf16.bf16.f32 "                \
        "{%0,%1,%2,%3}, {%4,%5,%6,%7}, {%8,%9}, {%0,%1,%2,%3};"               \
        : "+f"(d[0]), "+f"(d[1]), "+f"(d[2]), "+f"(d[3])                      \
        : "r"(a0), "r"(a1), "r"(a2), "r"(a3), "r"(b0), "r"(b1))

// ---------------- init: output only (colsum zeroed in prep) ----------------
__global__ void init_kernel(float* out) {
    if (blockIdx.x == 0 && threadIdx.x == 0) *out = 0.0f;
}

// ---------------- prep: per-speaker normalize + diag terms -----------------
__global__ __launch_bounds__(256) void prep_kernel(const float* __restrict__ v) {
    __shared__ float sv[M_UTT * D_EMB];
    __shared__ float red[8][33];
    __shared__ float fin[33];

    const int tid = threadIdx.x;
    const int n = blockIdx.x;

    if (tid < 16) g_colsum[n * 16 + tid] = 0.0f;   // zero for gemm atomics

    {
        const float4* src = (const float4*)(v + (size_t)n * M_UTT * D_EMB);
        float4* dst = (float4*)sv;
        #pragma unroll
        for (int i = 0; i < (M_UTT * D_EMB / 4) / 256; i++)
            dst[tid + i * 256] = src[tid + i * 256];
    }
    __syncthreads();

    float s0 = 0.0f, s1 = 0.0f;
    #pragma unroll
    for (int m = 0; m < M_UTT; m++) {
        s0 += sv[m * D_EMB + tid];
        s1 += sv[m * D_EMB + tid + 256];
    }

    float vals[33];
    #pragma unroll
    for (int m = 0; m < M_UTT; m++) {
        float x0 = sv[m * D_EMB + tid];
        float x1 = sv[m * D_EMB + tid + 256];
        vals[m]      = x0 * x0 + x1 * x1;
        vals[16 + m] = s0 * x0 + s1 * x1;
    }
    vals[32] = s0 * s0 + s1 * s1;

    #pragma unroll
    for (int i = 0; i < 33; i++) {
        float x = vals[i];
        #pragma unroll
        for (int o = 16; o > 0; o >>= 1) x += __shfl_xor_sync(0xffffffffu, x, o);
        vals[i] = x;
    }
    const int warp = tid >> 5, lane = tid & 31;
    if (lane == 0) {
        #pragma unroll
        for (int i = 0; i < 33; i++) red[warp][i] = vals[i];
    }
    __syncthreads();
    if (tid < 33) {
        float x = 0.0f;
        #pragma unroll
        for (int w = 0; w < 8; w++) x += red[w][tid];
        fin[tid] = x;
    }
    __syncthreads();

    const float ss = fin[32];
    const float cinv = 1.0f / fmaxf(sqrtf(ss), (float)M_UTT * EPSF);

    __nv_bfloat16 cb0 = __float2bfloat16(s0 * cinv);
    __nv_bfloat16 cb1 = __float2bfloat16(s1 * cinv);
    g_Cnb[n * D_EMB + tid]       = cb0;
    g_Cnb[n * D_EMB + tid + 256] = cb1;
    const float fc0 = __bfloat162float(cb0);
    const float fc1 = __bfloat162float(cb1);

    float sfp[16];
    #pragma unroll
    for (int m = 0; m < M_UTT; m++) {
        float rv = 1.0f / fmaxf(sqrtf(fin[m]), EPSF);
        __nv_bfloat16 vb0 = __float2bfloat16(sv[m * D_EMB + tid] * rv);
        __nv_bfloat16 vb1 = __float2bfloat16(sv[m * D_EMB + tid + 256] * rv);
        size_t base = (size_t)(n * M_UTT + m) * D_EMB;
        g_vnb[base + tid]       = vb0;
        g_vnb[base + tid + 256] = vb1;
        sfp[m] = fc0 * __bfloat162float(vb0) + fc1 * __bfloat162float(vb1);
    }

    #pragma unroll
    for (int m = 0; m < 16; m++) {
        float x = sfp[m];
        #pragma unroll
        for (int o = 16; o > 0; o >>= 1) x += __shfl_xor_sync(0xffffffffu, x, o);
        sfp[m] = x;
    }
    if (lane == 0) {
        #pragma unroll
        for (int m = 0; m < 16; m++) red[warp][m] = sfp[m];
    }
    __syncthreads();
    if (tid < 16) {
        float x = 0.0f;
        #pragma unroll
        for (int w = 0; w < 8; w++) x += red[w][tid];
        g_sself[n * M_UTT + tid] = x;

        float sq  = fin[tid];
        float dsv = fin[16 + tid];
        float nv  = fmaxf(sqrtf(sq), EPSF);
        float cm2 = fmaxf(ss - 2.0f * dsv + sq, 0.0f);
        const float invMm1 = 1.0f / (float)(M_UTT - 1);
        float ncm = fmaxf(sqrtf(cm2) * invMm1, EPSF);
        g_sdiag[n * M_UTT + tid] = ((dsv - sq) * invMm1) / (ncm * nv);
    }
}

// ---------------- persistent mma.sync GEMM + fused exp rowsum ---------------
// 2048 units = 256 mtiles(128 utt) x 8 ntiles(256 spk); 152 persistent CTAs,
// each owns a contiguous mtile-major unit range. A tile resident per mtile
// run; B double-buffered in BK=64 chunks; warp m64 x n64; rowsums flushed
// per mtile-run via atomicAdd.
#define A_PITCH 520
#define B_PITCH 72
#define SA_BYTES (128 * A_PITCH * 2)       // 133120
#define SB_BYTES (256 * B_PITCH * 2)       // 36864 per buffer
#define SB_OFF   SA_BYTES
#define SRED_OFF (SB_OFF + 2 * SB_BYTES)   // 206848
#define SMEM_SZ  (SRED_OFF + 4 * 128 * 4)  // 208896

__global__ __launch_bounds__(256, 1) void gemm_lse_kernel(const float* __restrict__ wp) {
    extern __shared__ char smem[];
    const uint32_t sbase = smem_u32(smem);
    const uint32_t* As32 = (const uint32_t*)smem;
    float* red = (float*)(smem + SRED_OFF);

    const int tid = threadIdx.x;
    const int lane = tid & 31, wid = tid >> 5;
    const int warpM = wid & 1;
    const int warpN = wid >> 1;
    const int qg = lane >> 2, t = lane & 3;

    const int start = (int)(((long long)blockIdx.x * NUNITS) / GRID_GEMM);
    const int end   = (int)(((long long)(blockIdx.x + 1) * NUNITS) / GRID_GEMM);

    const float wv = *wp;
    const float c1 = wv * 1.44269504f;
    const float c0 = -c1;

    auto loadB = [&](int ntile, int kc, int buf) {
        const __nv_bfloat16* bsrc = g_Cnb + (size_t)(ntile * 256) * D_EMB + kc * 64;
        const uint32_t bb = sbase + SB_OFF + buf * SB_BYTES;
        #pragma unroll
        for (int i = 0; i < 8; i++) {
            int flat = tid + 256 * i;
            int row = flat >> 3, k8 = flat & 7;
            cp16(bb + row * (B_PITCH * 2) + k8 * 16,
                 bsrc + (size_t)row * D_EMB + k8 * 8);
        }
    };

    float acc[4][8][4];
    #pragma unroll
    for (int i = 0; i < 4; i++)
        #pragma unroll
        for (int j = 0; j < 8; j++)
            #pragma unroll
            for (int r = 0; r < 4; r++) acc[i][j][r] = 0.0f;

    for (int g = start; g < end; ) {
        const int mt = g >> 3;
        const int run_end = min(end, (mt + 1) << 3);
        const int cnt = (run_end - g) * 8;            // >= 8, multiple of 8

        // ---- stage A for this mtile (group with B chunk 0) ----------------
        {
            const __nv_bfloat16* vsrc = g_vnb + (size_t)(mt * 128) * D_EMB;
            #pragma unroll 8
            for (int i = 0; i < 32; i++) {
                int flat = tid + 256 * i;
                int row = flat >> 6, cc = flat & 63;
                cp16(sbase + row * (A_PITCH * 2) + cc * 16,
                     vsrc + (size_t)row * D_EMB + cc * 8);
            }
        }
        loadB(g & 7, 0, 0); cp_commit();
        loadB((g + (1 >> 3)) & 7, 1, 1); cp_commit();  // chunk 1 (same unit)

        float rs[4][2] = {{0,0},{0,0},{0,0},{0,0}};

        #pragma unroll 1
        for (int c = 0; c < cnt; c++) {
            const int buf = c & 1;
            cp_wait1();
            __syncthreads();

            const uint32_t* B32 = (const uint32_t*)(smem + SB_OFF + buf * SB_BYTES);
            const int kcw = (c & 7) * 32;

            #pragma unroll
            for (int s = 0; s < 4; s++) {
                uint32_t ra[4][4];
                #pragma unroll
                for (int i = 0; i < 4; i++) {
                    const int arow = warpM * 64 + i * 16 + qg;
                    const int wi = arow * (A_PITCH / 2) + kcw + s * 8 + t;
                    ra[i][0] = As32[wi];
                    ra[i][1] = As32[wi + 8 * (A_PITCH / 2)];
                    ra[i][2] = As32[wi + 4];
                    ra[i][3] = As32[wi + 8 * (A_PITCH / 2) + 4];
                }
                #pragma unroll
                for (int j = 0; j < 8; j++) {
                    const int nrow = warpN * 64 + j * 8 + qg;
                    const int wj = nrow * (B_PITCH / 2) + s * 8 + t;
                    const uint32_t rb0 = B32[wj];
                    const uint32_t rb1 = B32[wj + 4];
                    #pragma unroll
                    for (int i = 0; i < 4; i++)
                        MMA_BF16(acc[i][j], ra[i][0], ra[i][1], ra[i][2], ra[i][3], rb0, rb1);
                }
            }

            __syncthreads();
            if (c + 2 < cnt) {
                const int c2 = c + 2;
                loadB((g + (c2 >> 3)) & 7, c2 & 7, buf);
            }
            cp_commit();

            if ((c & 7) == 7) {                        // unit done
                #pragma unroll
                for (int i = 0; i < 4; i++) {
                    float a0 = 0.0f, a1 = 0.0f;
                    #pragma unroll
                    for (int j = 0; j < 8; j++) {
                        a0 += ex2a(fmaf(acc[i][j][0], c1, c0)) + ex2a(fmaf(acc[i][j][1], c1, c0));
                        a1 += ex2a(fmaf(acc[i][j][2], c1, c0)) + ex2a(fmaf(acc[i][j][3], c1, c0));
                        acc[i][j][0] = acc[i][j][1] = acc[i][j][2] = acc[i][j][3] = 0.0f;
                    }
                    rs[i][0] += a0;
                    rs[i][1] += a1;
                }
            }
        }

        // ---- flush rowsums for this mtile run -----------------------------
        #pragma unroll
        for (int i = 0; i < 4; i++)
            #pragma unroll
            for (int r = 0; r < 2; r++) {
                float x = rs[i][r];
                x += __shfl_xor_sync(0xffffffffu, x, 1);
                x += __shfl_xor_sync(0xffffffffu, x, 2);
                rs[i][r] = x;
            }
        if (t == 0) {
            #pragma unroll
            for (int i = 0; i < 4; i++)
                #pragma unroll
                for (int r = 0; r < 2; r++)
                    red[warpN * 128 + warpM * 64 + i * 16 + r * 8 + qg] = rs[i][r];
        }
        __syncthreads();
        if (tid < 128)
            atomicAdd(&g_colsum[mt * 128 + tid],
                      (red[tid] + red[128 + tid]) + (red[256 + tid] + red[384 + tid]));
        __syncthreads();                               // red/A reuse next run

        g = run_end;
    }
}

// ---------------- final loss ------------------------------------------------
__global__ __launch_bounds__(256) void loss_kernel(const float* __restrict__ wp,
                                                   float* __restrict__ out) {
    __shared__ float rsm[8];
    const int j = blockIdx.x * blockDim.x + threadIdx.x;
    const float wv = *wp;
    const float c1 = wv * 1.44269504f;
    const float c0 = -c1;
    float L = 0.0f;
    if (j < NM) {
        float sd = g_sdiag[j];
        float sf = g_sself[j];
        float cs = g_colsum[j] - ex2a(fmaf(sf, c1, c0)) + ex2a(fmaf(sd, c1, c0));
        L = wv * (1.0f - sd) + logf(cs);
    }
    #pragma unroll
    for (int o = 16; o > 0; o >>= 1) L += __shfl_xor_sync(0xffffffffu, L, o);
    const int warp = threadIdx.x >> 5, lane = threadIdx.x & 31;
    if (lane == 0) rsm[warp] = L;
    __syncthreads();
    if (threadIdx.x == 0) {
        float tacc = 0.0f;
        #pragma unroll
        for (int w = 0; w < 8; w++) tacc += rsm[w];
        atomicAdd(out, tacc);
    }
}

// ---------------------------------------------------------------------------
extern "C" void kernel_launch(void* const* d_in, const int* in_sizes, int n_in,
                              void* d_out, int out_size) {
    const float* v  = (const float*)d_in[0];   // [NM, D] fp32
    const float* wp = (const float*)d_in[1];   // scalar w (b cancels analytically)
    float* out = (float*)d_out;

    cudaFuncSetAttribute(gemm_lse_kernel,
                         cudaFuncAttributeMaxDynamicSharedMemorySize, SMEM_SZ);

    init_kernel<<<1, 32>>>(out);
    prep_kernel<<<N_SPK, 256>>>(v);
    gemm_lse_kernel<<<GRID_GEMM, 256, SMEM_SZ>>>(wp);
    loss_kernel<<<NM / 256, 256>>>(wp, out);
}

// round 9
// speedup vs baseline: 1.2180x; 1.0137x over previous
#include <cuda_runtime.h>
#include <cuda_bf16.h>
#include <cstdint>
#include <math.h>

#define N_SPK 2048
#define M_UTT 16
#define D_EMB 512
#define NM (N_SPK * M_UTT)
#define EPSF 1e-8f
#define GRID_GEMM 152                  // GB300: 152 SMs, persistent 1 CTA/SM
#define NUNITS 2048                    // 256 mtiles x 8 ntiles

// ---------------- scratch (allocation-free rule: __device__ globals) -------
__device__ __nv_bfloat16 g_vnb[NM * D_EMB];     // normalized utterances, bf16
__device__ __nv_bfloat16 g_Cnb[N_SPK * D_EMB];  // normalized centroids,  bf16
__device__ float g_sdiag[NM];                   // cos(C_min[j], v_j) fp32-exact
__device__ float g_sself[NM];                   // dot of bf16-rounded Cn,vn
__device__ float g_colsum[NM];                  // sum_n exp(w*(S[n,j]-1))

// ---------------- helpers ---------------------------------------------------
__device__ __forceinline__ uint32_t smem_u32(const void* p) {
    uint32_t a;
    asm("{ .reg .u64 t; cvta.to.shared.u64 t, %1; cvt.u32.u64 %0, t; }" : "=r"(a) : "l"(p));
    return a;
}
__device__ __forceinline__ void cp16(uint32_t s, const void* g) {
    asm volatile("cp.async.cg.shared.global [%0], [%1], 16;" :: "r"(s), "l"(g) : "memory");
}
__device__ __forceinline__ void cp_commit() { asm volatile("cp.async.commit_group;" ::: "memory"); }
__device__ __forceinline__ void cp_wait1()  { asm volatile("cp.async.wait_group 1;" ::: "memory"); }
__device__ __forceinline__ float ex2a(float x) {
    float r; asm("ex2.approx.f32 %0, %1;" : "=f"(r) : "f"(x)); return r;
}
#define MMA_BF16(d, a0, a1, a2, a3, b0, b1)                                   \
    asm volatile(                                                             \
        "mma.sync.aligned.m16n8k16.row.col.f32.bf16.bf16.f32 "                \
        "{%0,%1,%2,%3}, {%4,%5,%6,%7}, {%8,%9}, {%0,%1,%2,%3};"               \
        : "+f"(d[0]), "+f"(d[1]), "+f"(d[2]), "+f"(d[3])                      \
        : "r"(a0), "r"(a1), "r"(a2), "r"(a3), "r"(b0), "r"(b1))
#define LDSM_X4(r0, r1, r2, r3, addr)                                         \
    asm volatile(                                                             \
        "ldmatrix.sync.aligned.m8n8.x4.shared.b16 {%0,%1,%2,%3}, [%4];"       \
        : "=r"(r0), "=r"(r1), "=r"(r2), "=r"(r3) : "r"(addr))

// ---------------- init: output only (colsum zeroed in prep) ----------------
__global__ void init_kernel(float* out) {
    if (blockIdx.x == 0 && threadIdx.x == 0) *out = 0.0f;
}

// ---------------- prep: per-speaker normalize + diag terms -----------------
__global__ __launch_bounds__(256) void prep_kernel(const float* __restrict__ v) {
    __shared__ float sv[M_UTT * D_EMB];
    __shared__ float red[8][33];
    __shared__ float fin[33];

    const int tid = threadIdx.x;
    const int n = blockIdx.x;

    if (tid < 16) g_colsum[n * 16 + tid] = 0.0f;   // zero for gemm atomics

    {
        const float4* src = (const float4*)(v + (size_t)n * M_UTT * D_EMB);
        float4* dst = (float4*)sv;
        #pragma unroll
        for (int i = 0; i < (M_UTT * D_EMB / 4) / 256; i++)
            dst[tid + i * 256] = src[tid + i * 256];
    }
    __syncthreads();

    float s0 = 0.0f, s1 = 0.0f;
    #pragma unroll
    for (int m = 0; m < M_UTT; m++) {
        s0 += sv[m * D_EMB + tid];
        s1 += sv[m * D_EMB + tid + 256];
    }

    float vals[33];
    #pragma unroll
    for (int m = 0; m < M_UTT; m++) {
        float x0 = sv[m * D_EMB + tid];
        float x1 = sv[m * D_EMB + tid + 256];
        vals[m]      = x0 * x0 + x1 * x1;
        vals[16 + m] = s0 * x0 + s1 * x1;
    }
    vals[32] = s0 * s0 + s1 * s1;

    #pragma unroll
    for (int i = 0; i < 33; i++) {
        float x = vals[i];
        #pragma unroll
        for (int o = 16; o > 0; o >>= 1) x += __shfl_xor_sync(0xffffffffu, x, o);
        vals[i] = x;
    }
    const int warp = tid >> 5, lane = tid & 31;
    if (lane == 0) {
        #pragma unroll
        for (int i = 0; i < 33; i++) red[warp][i] = vals[i];
    }
    __syncthreads();
    if (tid < 33) {
        float x = 0.0f;
        #pragma unroll
        for (int w = 0; w < 8; w++) x += red[w][tid];
        fin[tid] = x;
    }
    __syncthreads();

    const float ss = fin[32];
    const float cinv = 1.0f / fmaxf(sqrtf(ss), (float)M_UTT * EPSF);

    __nv_bfloat16 cb0 = __float2bfloat16(s0 * cinv);
    __nv_bfloat16 cb1 = __float2bfloat16(s1 * cinv);
    g_Cnb[n * D_EMB + tid]       = cb0;
    g_Cnb[n * D_EMB + tid + 256] = cb1;
    const float fc0 = __bfloat162float(cb0);
    const float fc1 = __bfloat162float(cb1);

    float sfp[16];
    #pragma unroll
    for (int m = 0; m < M_UTT; m++) {
        float rv = 1.0f / fmaxf(sqrtf(fin[m]), EPSF);
        __nv_bfloat16 vb0 = __float2bfloat16(sv[m * D_EMB + tid] * rv);
        __nv_bfloat16 vb1 = __float2bfloat16(sv[m * D_EMB + tid + 256] * rv);
        size_t base = (size_t)(n * M_UTT + m) * D_EMB;
        g_vnb[base + tid]       = vb0;
        g_vnb[base + tid + 256] = vb1;
        sfp[m] = fc0 * __bfloat162float(vb0) + fc1 * __bfloat162float(vb1);
    }

    #pragma unroll
    for (int m = 0; m < 16; m++) {
        float x = sfp[m];
        #pragma unroll
        for (int o = 16; o > 0; o >>= 1) x += __shfl_xor_sync(0xffffffffu, x, o);
        sfp[m] = x;
    }
    if (lane == 0) {
        #pragma unroll
        for (int m = 0; m < 16; m++) red[warp][m] = sfp[m];
    }
    __syncthreads();
    if (tid < 16) {
        float x = 0.0f;
        #pragma unroll
        for (int w = 0; w < 8; w++) x += red[w][tid];
        g_sself[n * M_UTT + tid] = x;

        float sq  = fin[tid];
        float dsv = fin[16 + tid];
        float nv  = fmaxf(sqrtf(sq), EPSF);
        float cm2 = fmaxf(ss - 2.0f * dsv + sq, 0.0f);
        const float invMm1 = 1.0f / (float)(M_UTT - 1);
        float ncm = fmaxf(sqrtf(cm2) * invMm1, EPSF);
        g_sdiag[n * M_UTT + tid] = ((dsv - sq) * invMm1) / (ncm * nv);
    }
}

// ---------------- persistent mma.sync GEMM + fused exp rowsum ---------------
// Same structure as R7 winner; fragment loads via ldmatrix.x4 (32 LDSM vs 128
// LDS.32 per warp per chunk). Pitches 1040B / 144B (both == 16 mod 128) keep
// every LDSM phase conflict-free.
#define A_PITCHB 1040                      // bytes per A row (520 bf16)
#define B_PITCHB 144                       // bytes per B row (72 bf16)
#define SA_BYTES (128 * A_PITCHB)          // 133120
#define SB_BYTES (256 * B_PITCHB)          // 36864 per buffer
#define SB_OFF   SA_BYTES
#define SRED_OFF (SB_OFF + 2 * SB_BYTES)   // 206848
#define SMEM_SZ  (SRED_OFF + 4 * 128 * 4)  // 208896

__global__ __launch_bounds__(256, 1) void gemm_lse_kernel(const float* __restrict__ wp) {
    extern __shared__ char smem[];
    const uint32_t sbase = smem_u32(smem);
    float* red = (float*)(smem + SRED_OFF);

    const int tid = threadIdx.x;
    const int lane = tid & 31, wid = tid >> 5;
    const int warpM = wid & 1;
    const int warpN = wid >> 1;
    const int qg = lane >> 2, t = lane & 3;
    const int mat = lane >> 3, rr = lane & 7;   // ldmatrix address roles

    const int start = (int)(((long long)blockIdx.x * NUNITS) / GRID_GEMM);
    const int end   = (int)(((long long)(blockIdx.x + 1) * NUNITS) / GRID_GEMM);

    const float wv = *wp;
    const float c1 = wv * 1.44269504f;
    const float c0 = -c1;

    // ldmatrix per-lane base addresses
    // A x4 for i: matrices (r0: rows 0-7,k0-7)(r1: rows 8-15,k0-7)
    //             (r2: rows 0-7,k8-15)(r3: rows 8-15,k8-15)
    uint32_t aAddr[4];
    #pragma unroll
    for (int i = 0; i < 4; i++)
        aAddr[i] = sbase + (uint32_t)(warpM * 64 + i * 16 + (mat & 1) * 8 + rr) * A_PITCHB
                 + (uint32_t)(mat >> 1) * 16;
    // B x4 for j2: (r0: j rows,k0-7)(r1: j rows,k8-15)(r2: j+1 rows,k0-7)(r3: j+1,k8-15)
    uint32_t bAddr[4];
    #pragma unroll
    for (int j2 = 0; j2 < 4; j2++)
        bAddr[j2] = sbase + SB_OFF
                  + (uint32_t)(warpN * 64 + j2 * 16 + (mat >> 1) * 8 + rr) * B_PITCHB
                  + (uint32_t)(mat & 1) * 16;

    auto loadB = [&](int ntile, int kc, int buf) {
        const __nv_bfloat16* bsrc = g_Cnb + (size_t)(ntile * 256) * D_EMB + kc * 64;
        const uint32_t bb = sbase + SB_OFF + buf * SB_BYTES;
        #pragma unroll
        for (int i = 0; i < 8; i++) {
            int flat = tid + 256 * i;
            int row = flat >> 3, k8 = flat & 7;
            cp16(bb + row * B_PITCHB + k8 * 16,
                 bsrc + (size_t)row * D_EMB + k8 * 8);
        }
    };

    float acc[4][8][4];
    #pragma unroll
    for (int i = 0; i < 4; i++)
        #pragma unroll
        for (int j = 0; j < 8; j++)
            #pragma unroll
            for (int r = 0; r < 4; r++) acc[i][j][r] = 0.0f;

    for (int g = start; g < end; ) {
        const int mt = g >> 3;
        const int run_end = min(end, (mt + 1) << 3);
        const int cnt = (run_end - g) * 8;

        // ---- stage A for this mtile (group with B chunk 0) ----------------
        {
            const __nv_bfloat16* vsrc = g_vnb + (size_t)(mt * 128) * D_EMB;
            #pragma unroll 8
            for (int i = 0; i < 32; i++) {
                int flat = tid + 256 * i;
                int row = flat >> 6, cc = flat & 63;
                cp16(sbase + row * A_PITCHB + cc * 16,
                     vsrc + (size_t)row * D_EMB + cc * 8);
            }
        }
        loadB(g & 7, 0, 0); cp_commit();
        loadB(g & 7, 1, 1); cp_commit();

        float rs[4][2] = {{0,0},{0,0},{0,0},{0,0}};

        #pragma unroll 1
        for (int c = 0; c < cnt; c++) {
            const int buf = c & 1;
            cp_wait1();
            __syncthreads();

            const uint32_t kcB = (uint32_t)(c & 7) * 128;
            const uint32_t bOff = (uint32_t)buf * SB_BYTES;

            #pragma unroll
            for (int s = 0; s < 4; s++) {
                uint32_t ra[4][4];
                #pragma unroll
                for (int i = 0; i < 4; i++)
                    LDSM_X4(ra[i][0], ra[i][1], ra[i][2], ra[i][3],
                            aAddr[i] + kcB + s * 32);
                #pragma unroll
                for (int j2 = 0; j2 < 4; j2++) {
                    uint32_t rb0, rb1, rb2, rb3;
                    LDSM_X4(rb0, rb1, rb2, rb3, bAddr[j2] + bOff + s * 32);
                    #pragma unroll
                    for (int i = 0; i < 4; i++) {
                        MMA_BF16(acc[i][2 * j2],     ra[i][0], ra[i][1], ra[i][2], ra[i][3], rb0, rb1);
                        MMA_BF16(acc[i][2 * j2 + 1], ra[i][0], ra[i][1], ra[i][2], ra[i][3], rb2, rb3);
                    }
                }
            }

            __syncthreads();
            if (c + 2 < cnt) {
                const int c2 = c + 2;
                loadB((g + (c2 >> 3)) & 7, c2 & 7, buf);
            }
            cp_commit();

            if ((c & 7) == 7) {                        // unit done: exp rowsums
                #pragma unroll
                for (int i = 0; i < 4; i++) {
                    float a0 = 0.0f, a1 = 0.0f;
                    #pragma unroll
                    for (int j = 0; j < 8; j++) {
                        a0 += ex2a(fmaf(acc[i][j][0], c1, c0)) + ex2a(fmaf(acc[i][j][1], c1, c0));
                        a1 += ex2a(fmaf(acc[i][j][2], c1, c0)) + ex2a(fmaf(acc[i][j][3], c1, c0));
                        acc[i][j][0] = acc[i][j][1] = acc[i][j][2] = acc[i][j][3] = 0.0f;
                    }
                    rs[i][0] += a0;
                    rs[i][1] += a1;
                }
            }
        }

        // ---- flush rowsums for this mtile run -----------------------------
        #pragma unroll
        for (int i = 0; i < 4; i++)
            #pragma unroll
            for (int r = 0; r < 2; r++) {
                float x = rs[i][r];
                x += __shfl_xor_sync(0xffffffffu, x, 1);
                x += __shfl_xor_sync(0xffffffffu, x, 2);
                rs[i][r] = x;
            }
        if (t == 0) {
            #pragma unroll
            for (int i = 0; i < 4; i++)
                #pragma unroll
                for (int r = 0; r < 2; r++)
                    red[warpN * 128 + warpM * 64 + i * 16 + r * 8 + qg] = rs[i][r];
        }
        __syncthreads();
        if (tid < 128)
            atomicAdd(&g_colsum[mt * 128 + tid],
                      (red[tid] + red[128 + tid]) + (red[256 + tid] + red[384 + tid]));
        __syncthreads();                               // red/A reuse next run

        g = run_end;
    }
}

// ---------------- final loss ------------------------------------------------
__global__ __launch_bounds__(256) void loss_kernel(const float* __restrict__ wp,
                                                   float* __restrict__ out) {
    __shared__ float rsm[8];
    const int j = blockIdx.x * blockDim.x + threadIdx.x;
    const float wv = *wp;
    const float c1 = wv * 1.44269504f;
    const float c0 = -c1;
    float L = 0.0f;
    if (j < NM) {
        float sd = g_sdiag[j];
        float sf = g_sself[j];
        float cs = g_colsum[j] - ex2a(fmaf(sf, c1, c0)) + ex2a(fmaf(sd, c1, c0));
        L = wv * (1.0f - sd) + logf(cs);
    }
    #pragma unroll
    for (int o = 16; o > 0; o >>= 1) L += __shfl_xor_sync(0xffffffffu, L, o);
    const int warp = threadIdx.x >> 5, lane = threadIdx.x & 31;
    if (lane == 0) rsm[warp] = L;
    __syncthreads();
    if (threadIdx.x == 0) {
        float tacc = 0.0f;
        #pragma unroll
        for (int w = 0; w < 8; w++) tacc += rsm[w];
        atomicAdd(out, tacc);
    }
}

// ---------------------------------------------------------------------------
extern "C" void kernel_launch(void* const* d_in, const int* in_sizes, int n_in,
                              void* d_out, int out_size) {
    const float* v  = (const float*)d_in[0];   // [NM, D] fp32
    const float* wp = (const float*)d_in[1];   // scalar w (b cancels analytically)
    float* out = (float*)d_out;

    cudaFuncSetAttribute(gemm_lse_kernel,
                         cudaFuncAttributeMaxDynamicSharedMemorySize, SMEM_SZ);

    init_kernel<<<1, 32>>>(out);
    prep_kernel<<<N_SPK, 256>>>(v);
    gemm_lse_kernel<<<GRID_GEMM, 256, SMEM_SZ>>>(wp);
    loss_kernel<<<NM / 256, 256>>>(wp, out);
}